// round 16
// baseline (speedup 1.0000x reference)
#include <cuda_runtime.h>
#include <cuda_bf16.h>
#include <math.h>
#include <stdint.h>

#define BSZ 8
#define CCH 256
#define NSP 1024
#define NHH 4
#define DKD 64
#define CNT (CCH*NSP)

__device__ float g_sums1[2*BSZ];
__device__ float g_sums2[2*BSZ];
__device__ float g_attn[(size_t)BSZ*CCH*NSP];
__device__ float g_x2  [(size_t)BSZ*CCH*NSP];

// split-bf16 qkv outputs in attention-native layouts
__device__ __nv_bfloat16 g_qkH[(size_t)BSZ*NSP*512];   // [b][tok][0..255=Q(pre-scaled),256..511=K]
__device__ __nv_bfloat16 g_qkL[(size_t)BSZ*NSP*512];
__device__ __nv_bfloat16 g_vH [(size_t)BSZ*CCH*NSP];   // [b][vch][tok]
__device__ __nv_bfloat16 g_vL [(size_t)BSZ*CCH*NSP];
// preconverted normalized activations, token-major [b][tok][256]
__device__ __nv_bfloat16 g_aH[(size_t)BSZ*NSP*CCH];
__device__ __nv_bfloat16 g_aL[(size_t)BSZ*NSP*CCH];
// h1 split-bf16 token-major [b][tok][1024]
__device__ __nv_bfloat16 g_h1H[(size_t)BSZ*NSP*1024];
__device__ __nv_bfloat16 g_h1L[(size_t)BSZ*NSP*1024];

// preconverted split-bf16 weights
#define W_QKV 0
#define W_UH  196608
#define W_F1  262144
#define W_F2  524288
__device__ __nv_bfloat16 g_wH[786432];
__device__ __nv_bfloat16 g_wL[786432];

// ---------- reductions / stats ----------
__device__ __forceinline__ void block_reduce2(float& s, float& s2) {
    #pragma unroll
    for (int o = 16; o; o >>= 1) {
        s  += __shfl_xor_sync(0xffffffffu, s,  o);
        s2 += __shfl_xor_sync(0xffffffffu, s2, o);
    }
    __shared__ float sh0[8], sh1[8];
    int w = threadIdx.x >> 5, l = threadIdx.x & 31;
    if (l == 0) { sh0[w] = s; sh1[w] = s2; }
    __syncthreads();
    if (w == 0) {
        s  = (l < 8) ? sh0[l] : 0.f;
        s2 = (l < 8) ? sh1[l] : 0.f;
        #pragma unroll
        for (int o = 4; o; o >>= 1) {
            s  += __shfl_xor_sync(0xffffffffu, s,  o);
            s2 += __shfl_xor_sync(0xffffffffu, s2, o);
        }
    }
}

__global__ void zero_stats_kernel() {
    int t = threadIdx.x;
    if (t < 2*BSZ) { g_sums1[t] = 0.f; g_sums2[t] = 0.f; }
}

__global__ void gn_stats_kernel(const float* __restrict__ x) {
    int b = blockIdx.y;
    const float* xb = x + (size_t)b * CNT;
    int base = blockIdx.x * (CNT / 32);
    float s = 0.f, s2 = 0.f;
    for (int i = threadIdx.x; i < CNT/32; i += 256) {
        float v = xb[base + i];
        s += v; s2 += v*v;
    }
    block_reduce2(s, s2);
    if (threadIdx.x == 0) {
        atomicAdd(&g_sums1[b*2],   s);
        atomicAdd(&g_sums1[b*2+1], s2);
    }
}

// ---------- helpers ----------
#define MMA_B16(c, a, b0, b1) \
  asm volatile("mma.sync.aligned.m16n8k16.row.col.f32.bf16.bf16.f32 " \
    "{%0,%1,%2,%3}, {%4,%5,%6,%7}, {%8,%9}, {%0,%1,%2,%3};" \
    : "+f"((c)[0]),"+f"((c)[1]),"+f"((c)[2]),"+f"((c)[3]) \
    : "r"((a)[0]),"r"((a)[1]),"r"((a)[2]),"r"((a)[3]), "r"(b0),"r"(b1))

__device__ __forceinline__ void ldsm4(uint32_t& r0, uint32_t& r1, uint32_t& r2,
                                      uint32_t& r3, uint32_t addr) {
    asm volatile("ldmatrix.sync.aligned.m8n8.x4.shared.b16 {%0,%1,%2,%3}, [%4];"
        : "=r"(r0), "=r"(r1), "=r"(r2), "=r"(r3) : "r"(addr));
}
__device__ __forceinline__ uint32_t s2u(const void* p) {
    return (uint32_t)__cvta_generic_to_shared(p);
}
__device__ __forceinline__ void split_bf16(float v, __nv_bfloat16& h, __nv_bfloat16& l) {
    h = __float2bfloat16(v);
    l = __float2bfloat16(v - __bfloat162float(h));
}
__device__ __forceinline__ void pack2(float a, float b, uint32_t& h, uint32_t& l) {
    __nv_bfloat162 hb = __floats2bfloat162_rn(a, b);
    float ra = a - __bfloat162float(hb.x);
    float rb = b - __bfloat162float(hb.y);
    __nv_bfloat162 lb = __floats2bfloat162_rn(ra, rb);
    h = *(uint32_t*)&hb; l = *(uint32_t*)&lb;
}
#define CP16(dst, src) \
    asm volatile("cp.async.cg.shared.global [%0], [%1], 16;" :: "r"(dst), "l"(src) : "memory")

// merged one-shot weight split
__global__ void convert_w_all(const float* __restrict__ qkv_w, const float* __restrict__ uh_w,
                              const float* __restrict__ f1_w, const float* __restrict__ f2_w) {
    int i = blockIdx.x * blockDim.x + threadIdx.x;
    if (i >= 393216) return;
    const float* src; int li, base;
    if      (i <  98304) { src = qkv_w; li = i;          base = W_QKV; }
    else if (i < 131072) { src = uh_w;  li = i -  98304; base = W_UH;  }
    else if (i < 262144) { src = f1_w;  li = i - 131072; base = W_F1;  }
    else                 { src = f2_w;  li = i - 262144; base = W_F2;  }
    float2 f = *(const float2*)(src + 2*li);
    uint32_t H, L;
    pack2(f.x, f.y, H, L);
    *(uint32_t*)(g_wH + base + 2*li) = H;
    *(uint32_t*)(g_wL + base + 2*li) = L;
}

// GN + split + transpose: src [b][256][1024] fp32 -> g_aH/g_aL [b][tok][256]
template<int NORM>
__global__ void prep_act(const float* __restrict__ src,
                         const float* __restrict__ gw, const float* __restrict__ gb) {
    __shared__ float tile[32][33];
    int b = blockIdx.z;
    int c0 = blockIdx.y * 32, t0v = blockIdx.x * 32;
    int tx = threadIdx.x & 31, ty = threadIdx.x >> 5;
    const float* sums = (NORM == 1) ? g_sums1 : g_sums2;
    float mean = sums[b*2] * (1.f/CNT);
    float rstd = rsqrtf(sums[b*2+1] * (1.f/CNT) - mean*mean + 1e-5f);
    #pragma unroll
    for (int r = 0; r < 4; r++) {
        int ch = c0 + ty + 8*r;
        float gwc = gw[ch]*rstd, gbc = gb[ch] - mean*gwc;
        tile[ty + 8*r][tx] = src[((size_t)b*CCH + ch)*NSP + t0v + tx] * gwc + gbc;
    }
    __syncthreads();
    #pragma unroll
    for (int r = 0; r < 4; r++) {
        int tok = t0v + ty + 8*r;
        float v = tile[tx][ty + 8*r];
        __nv_bfloat16 h, l; split_bf16(v, h, l);
        size_t o = ((size_t)b*NSP + tok)*CCH + c0 + tx;
        g_aH[o] = h; g_aL[o] = l;
    }
}

#define ALD 72

// ---------- gemm_cp: all operands preconverted split-bf16, pure cp.async staging ----------
// single-buffered (73.7KB -> 2 CTA/SM). KD = K of gemm = row stride of W and act.
// EPI: 0 qkv-split-out, 3 bias+resid*g (final), 4 bias+silu -> token-major split h1
template<int KD, int EPI>
__global__ void __launch_bounds__(256) gemm_cp(
    const __nv_bfloat16* __restrict__ WH, const __nv_bfloat16* __restrict__ WL,
    const __nv_bfloat16* __restrict__ AH, const __nv_bfloat16* __restrict__ AL,
    const float* __restrict__ bias, const float* __restrict__ resid,
    const float* __restrict__ gamma, float* __restrict__ out)
{
    extern __shared__ __nv_bfloat16 smg[];
    __nv_bfloat16* AsH = smg;                 // weights [m][k]
    __nv_bfloat16* AsL = AsH + 128*ALD;
    __nv_bfloat16* BsH = AsL + 128*ALD;       // acts [tok][k]
    __nv_bfloat16* BsL = BsH + 128*ALD;

    int tid = threadIdx.x, lane = tid & 31, w = tid >> 5;
    int wm = w & 3, wn = w >> 2;
    int t0 = blockIdx.x * 128, m0 = blockIdx.y * 128, b = blockIdx.z;

    float acc[2][8][4] = {};
    const int g = lane >> 2, tq = lane & 3;
    const int lrow = lane & 7, lt = lane >> 3;
    const uint32_t a_off = (uint32_t)((wm*32 + ((lt & 1) << 3) + lrow) * (ALD*2) + (lt >> 1) * 16);
    const uint32_t b_off = (uint32_t)(((wn*64) + ((lt >> 1) << 3) + lrow) * (ALD*2) + (lt & 1) * 16);
    const uint32_t uAH = s2u(AsH), uAL = s2u(AsL);
    const uint32_t uBH = s2u(BsH), uBL = s2u(BsL);

    const int sm_m = tid >> 1, sm_kh = (tid & 1) * 32;
    const uint32_t sdst = (uint32_t)(sm_m*ALD + sm_kh)*2;
    const __nv_bfloat16* aHb = AH + ((size_t)b*NSP + t0 + sm_m)*KD + sm_kh;
    const __nv_bfloat16* aLb = AL + ((size_t)b*NSP + t0 + sm_m)*KD + sm_kh;
    const __nv_bfloat16* wHb = WH + (size_t)(m0 + sm_m)*KD + sm_kh;
    const __nv_bfloat16* wLb = WL + (size_t)(m0 + sm_m)*KD + sm_kh;

    for (int c = 0; c < KD/64; c++) {
        int kc = c * 64;
        {
            const __nv_bfloat16* pH = wHb + kc;
            const __nv_bfloat16* pL = wLb + kc;
            uint32_t dH = uAH + sdst, dL = uAL + sdst;
            CP16(dH, pH); CP16(dH+16, pH+8); CP16(dH+32, pH+16); CP16(dH+48, pH+24);
            CP16(dL, pL); CP16(dL+16, pL+8); CP16(dL+32, pL+16); CP16(dL+48, pL+24);
            const __nv_bfloat16* qH = aHb + kc;
            const __nv_bfloat16* qL = aLb + kc;
            uint32_t eH = uBH + sdst, eL = uBL + sdst;
            CP16(eH, qH); CP16(eH+16, qH+8); CP16(eH+32, qH+16); CP16(eH+48, qH+24);
            CP16(eL, qL); CP16(eL+16, qL+8); CP16(eL+32, qL+16); CP16(eL+48, qL+24);
            asm volatile("cp.async.commit_group;" ::: "memory");
        }
        asm volatile("cp.async.wait_group 0;" ::: "memory");
        __syncthreads();

        #pragma unroll
        for (int k4 = 0; k4 < 4; k4++) {
            uint32_t aHf[2][4], aLf[2][4];
            #pragma unroll
            for (int mf = 0; mf < 2; mf++) {
                ldsm4(aHf[mf][0], aHf[mf][1], aHf[mf][2], aHf[mf][3],
                      uAH + a_off + mf*16*(ALD*2) + k4*32);
                ldsm4(aLf[mf][0], aLf[mf][1], aLf[mf][2], aLf[mf][3],
                      uAL + a_off + mf*16*(ALD*2) + k4*32);
            }
            #pragma unroll
            for (int p = 0; p < 4; p++) {
                uint32_t h0, h1, h2, h3, x0, x1, x2, x3;
                ldsm4(h0, h1, h2, h3, uBH + b_off + p*16*(ALD*2) + k4*32);
                ldsm4(x0, x1, x2, x3, uBL + b_off + p*16*(ALD*2) + k4*32);
                #pragma unroll
                for (int mf = 0; mf < 2; mf++) {
                    MMA_B16(acc[mf][2*p  ], aHf[mf], h0, h1);
                    MMA_B16(acc[mf][2*p  ], aHf[mf], x0, x1);
                    MMA_B16(acc[mf][2*p  ], aLf[mf], h0, h1);
                    MMA_B16(acc[mf][2*p+1], aHf[mf], h2, h3);
                    MMA_B16(acc[mf][2*p+1], aHf[mf], x2, x3);
                    MMA_B16(acc[mf][2*p+1], aLf[mf], h2, h3);
                }
            }
        }
        __syncthreads();
    }

    if (EPI == 0) {
        if (m0 < 512) {
            __nv_bfloat16* EH = smg;             // [128 tok][136]
            __nv_bfloat16* EL = smg + 128*136;
            float scale = (m0 < 256) ? 0.125f : 1.f;
            #pragma unroll
            for (int mf = 0; mf < 2; mf++) {
                int chl = wm*32 + mf*16 + g;
                #pragma unroll
                for (int nf = 0; nf < 8; nf++) {
                    int tokl = wn*64 + nf*8 + tq*2;
                    __nv_bfloat16 h, l;
                    split_bf16(acc[mf][nf][0]*scale, h, l);
                    EH[ tokl   *136 + chl    ] = h; EL[ tokl   *136 + chl    ] = l;
                    split_bf16(acc[mf][nf][1]*scale, h, l);
                    EH[(tokl+1)*136 + chl    ] = h; EL[(tokl+1)*136 + chl    ] = l;
                    split_bf16(acc[mf][nf][2]*scale, h, l);
                    EH[ tokl   *136 + chl + 8] = h; EL[ tokl   *136 + chl + 8] = l;
                    split_bf16(acc[mf][nf][3]*scale, h, l);
                    EH[(tokl+1)*136 + chl + 8] = h; EL[(tokl+1)*136 + chl + 8] = l;
                }
            }
            __syncthreads();
            int tok = tid >> 1, half = (tid & 1) * 64;
            size_t o = ((size_t)b*NSP + t0 + tok)*512 + m0 + half;
            #pragma unroll
            for (int j = 0; j < 8; j++) {
                *(uint4*)(g_qkH + o + j*8) = *(const uint4*)&EH[tok*136 + half + j*8];
                *(uint4*)(g_qkL + o + j*8) = *(const uint4*)&EL[tok*136 + half + j*8];
            }
        } else {
            #pragma unroll
            for (int mf = 0; mf < 2; mf++) {
                int row = (m0 - 512) + wm*32 + mf*16 + g;
                #pragma unroll
                for (int nf = 0; nf < 8; nf++) {
                    int col = t0 + wn*64 + nf*8 + tq*2;
                    uint32_t H, L;
                    pack2(acc[mf][nf][0], acc[mf][nf][1], H, L);
                    size_t i0 = ((size_t)b*CCH + row)*NSP + col;
                    *(uint32_t*)(g_vH + i0) = H; *(uint32_t*)(g_vL + i0) = L;
                    pack2(acc[mf][nf][2], acc[mf][nf][3], H, L);
                    size_t i8 = ((size_t)b*CCH + row + 8)*NSP + col;
                    *(uint32_t*)(g_vH + i8) = H; *(uint32_t*)(g_vL + i8) = L;
                }
            }
        }
        return;
    }

    if (EPI == 4) {
        // bias + silu, transpose, write token-major split h1 [b][tok][1024]
        __nv_bfloat16* EH = smg;
        __nv_bfloat16* EL = smg + 128*136;
        #pragma unroll
        for (int mf = 0; mf < 2; mf++) {
            int chl = wm*32 + mf*16 + g;
            float b0 = bias[m0 + chl], b8 = bias[m0 + chl + 8];
            #pragma unroll
            for (int nf = 0; nf < 8; nf++) {
                int tokl = wn*64 + nf*8 + tq*2;
                float v0 = acc[mf][nf][0] + b0; v0 = v0 / (1.f + __expf(-v0));
                float v1 = acc[mf][nf][1] + b0; v1 = v1 / (1.f + __expf(-v1));
                float v2 = acc[mf][nf][2] + b8; v2 = v2 / (1.f + __expf(-v2));
                float v3 = acc[mf][nf][3] + b8; v3 = v3 / (1.f + __expf(-v3));
                __nv_bfloat16 h, l;
                split_bf16(v0, h, l);
                EH[ tokl   *136 + chl    ] = h; EL[ tokl   *136 + chl    ] = l;
                split_bf16(v1, h, l);
                EH[(tokl+1)*136 + chl    ] = h; EL[(tokl+1)*136 + chl    ] = l;
                split_bf16(v2, h, l);
                EH[ tokl   *136 + chl + 8] = h; EL[ tokl   *136 + chl + 8] = l;
                split_bf16(v3, h, l);
                EH[(tokl+1)*136 + chl + 8] = h; EL[(tokl+1)*136 + chl + 8] = l;
            }
        }
        __syncthreads();
        int tok = tid >> 1, half = (tid & 1) * 64;
        size_t o = ((size_t)b*NSP + t0 + tok)*1024 + m0 + half;
        #pragma unroll
        for (int j = 0; j < 8; j++) {
            *(uint4*)(g_h1H + o + j*8) = *(const uint4*)&EH[tok*136 + half + j*8];
            *(uint4*)(g_h1L + o + j*8) = *(const uint4*)&EL[tok*136 + half + j*8];
        }
        return;
    }

    // EPI == 3: bias + resid*gamma, fp32 channel-major out (MT=256)
    float gm = gamma[0];
    #pragma unroll
    for (int mf = 0; mf < 2; mf++) {
        int row = m0 + wm*32 + mf*16 + g;
        float bi0 = bias[row], bi8 = bias[row + 8];
        #pragma unroll
        for (int nf = 0; nf < 8; nf++) {
            int col = t0 + wn*64 + nf*8 + tq*2;
            size_t i0 = ((size_t)b*CCH + row    )*NSP + col;
            size_t i8 = ((size_t)b*CCH + row + 8)*NSP + col;
            float2 r0 = *(const float2*)(resid + i0);
            float2 r8 = *(const float2*)(resid + i8);
            float v00 = r0.x + gm*(acc[mf][nf][0] + bi0);
            float v01 = r0.y + gm*(acc[mf][nf][1] + bi0);
            float v10 = r8.x + gm*(acc[mf][nf][2] + bi8);
            float v11 = r8.y + gm*(acc[mf][nf][3] + bi8);
            *(float2*)(out + i0) = make_float2(v00, v01);
            *(float2*)(out + i8) = make_float2(v10, v11);
        }
    }
}

// ---------- gemm_mma (legacy transpose-convert path; uh only) ----------
template<int K, int EPI>
__global__ void __launch_bounds__(256) gemm_mma(
    const float* __restrict__ Act,
    const __nv_bfloat16* __restrict__ WH, const __nv_bfloat16* __restrict__ WL,
    const float* __restrict__ bias, const float* __restrict__ resid,
    const float* __restrict__ gamma, float* __restrict__ out)
{
    extern __shared__ __nv_bfloat16 smg[];
    __nv_bfloat16* AsH = smg;
    __nv_bfloat16* AsL = AsH + 128*ALD;
    __nv_bfloat16* BsH = AsL + 128*ALD;
    __nv_bfloat16* BsL = BsH + 128*ALD;

    int tid = threadIdx.x, lane = tid & 31, w = tid >> 5;
    int wm = w & 3, wn = w >> 2;
    int t0 = blockIdx.x * 128, m0 = blockIdx.y * 128, b = blockIdx.z;

    float acc[2][8][4] = {};
    const int g = lane >> 2, tq = lane & 3;
    const int lrow = lane & 7, lt = lane >> 3;
    const uint32_t a_off = (uint32_t)((wm*32 + ((lt & 1) << 3) + lrow) * (ALD*2) + (lt >> 1) * 16);
    const uint32_t b_off = (uint32_t)(((wn*64) + ((lt >> 1) << 3) + lrow) * (ALD*2) + (lt & 1) * 16);
    const uint32_t uAH = s2u(AsH), uAL = s2u(AsL);
    const uint32_t uBH = s2u(BsH), uBL = s2u(BsL);

    const int sm_m = tid >> 1, sm_kh = (tid & 1) * 32;
    const int sdp = tid & 31, stg = tid >> 5;

    for (int c = 0; c < K/64; c++) {
        int kc = c * 64;
        {
            const __nv_bfloat16* pH = WH + (size_t)(m0 + sm_m)*K + kc + sm_kh;
            const __nv_bfloat16* pL = WL + (size_t)(m0 + sm_m)*K + kc + sm_kh;
            uint32_t dH = uAH + (uint32_t)(sm_m*ALD + sm_kh)*2;
            uint32_t dL = uAL + (uint32_t)(sm_m*ALD + sm_kh)*2;
            CP16(dH, pH); CP16(dH+16, pH+8); CP16(dH+32, pH+16); CP16(dH+48, pH+24);
            CP16(dL, pL); CP16(dL+16, pL+8); CP16(dL+32, pL+16); CP16(dL+48, pL+24);
            asm volatile("cp.async.commit_group;" ::: "memory");
        }
        {
            int ch = kc + 2*sdp;
            const float* p0 = Act + ((size_t)b*K + ch)*NSP + t0 + stg*16;
            const float* p1 = p0 + NSP;
            #pragma unroll
            for (int qd = 0; qd < 4; qd++) {
                float4 fa = *(const float4*)(p0 + qd*4);
                float4 fb = *(const float4*)(p1 + qd*4);
                float va[4] = {fa.x, fa.y, fa.z, fa.w};
                float vbb[4] = {fb.x, fb.y, fb.z, fb.w};
                #pragma unroll
                for (int e = 0; e < 4; e++) {
                    int tok = stg*16 + qd*4 + e;
                    uint32_t H, L;
                    pack2(va[e], vbb[e], H, L);
                    *(uint32_t*)&BsH[tok*ALD + 2*sdp] = H;
                    *(uint32_t*)&BsL[tok*ALD + 2*sdp] = L;
                }
            }
        }
        asm volatile("cp.async.wait_group 0;" ::: "memory");
        __syncthreads();

        #pragma unroll
        for (int k4 = 0; k4 < 4; k4++) {
            uint32_t aH[2][4], aL[2][4];
            #pragma unroll
            for (int mf = 0; mf < 2; mf++) {
                ldsm4(aH[mf][0], aH[mf][1], aH[mf][2], aH[mf][3],
                      uAH + a_off + mf*16*(ALD*2) + k4*32);
                ldsm4(aL[mf][0], aL[mf][1], aL[mf][2], aL[mf][3],
                      uAL + a_off + mf*16*(ALD*2) + k4*32);
            }
            #pragma unroll
            for (int p = 0; p < 4; p++) {
                uint32_t h0, h1, h2, h3, x0, x1, x2, x3;
                ldsm4(h0, h1, h2, h3, uBH + b_off + p*16*(ALD*2) + k4*32);
                ldsm4(x0, x1, x2, x3, uBL + b_off + p*16*(ALD*2) + k4*32);
                #pragma unroll
                for (int mf = 0; mf < 2; mf++) {
                    MMA_B16(acc[mf][2*p  ], aH[mf], h0, h1);
                    MMA_B16(acc[mf][2*p  ], aH[mf], x0, x1);
                    MMA_B16(acc[mf][2*p  ], aL[mf], h0, h1);
                    MMA_B16(acc[mf][2*p+1], aH[mf], h2, h3);
                    MMA_B16(acc[mf][2*p+1], aH[mf], x2, x3);
                    MMA_B16(acc[mf][2*p+1], aL[mf], h2, h3);
                }
            }
        }
        __syncthreads();
    }

    float gm = gamma[0];
    float s1 = 0.f, sq = 0.f;
    #pragma unroll
    for (int mf = 0; mf < 2; mf++) {
        int row = m0 + wm*32 + mf*16 + g;
        float bi0 = bias[row], bi8 = bias[row + 8];
        #pragma unroll
        for (int nf = 0; nf < 8; nf++) {
            int col = t0 + wn*64 + nf*8 + tq*2;
            float v00 = acc[mf][nf][0] + bi0;
            float v01 = acc[mf][nf][1] + bi0;
            float v10 = acc[mf][nf][2] + bi8;
            float v11 = acc[mf][nf][3] + bi8;
            size_t i0 = ((size_t)b*CCH + row    )*NSP + col;
            size_t i8 = ((size_t)b*CCH + row + 8)*NSP + col;
            float2 r0 = *(const float2*)(resid + i0);
            float2 r8 = *(const float2*)(resid + i8);
            v00 = r0.x + gm*v00;  v01 = r0.y + gm*v01;
            v10 = r8.x + gm*v10;  v11 = r8.y + gm*v11;
            if (EPI == 1) {
                s1 += v00+v01+v10+v11;
                sq += v00*v00 + v01*v01 + v10*v10 + v11*v11;
            }
            *(float2*)(out + i0) = make_float2(v00, v01);
            *(float2*)(out + i8) = make_float2(v10, v11);
        }
    }
    if (EPI == 1) {
        block_reduce2(s1, sq);
        if (tid == 0) { atomicAdd(&g_sums2[b*2], s1); atomicAdd(&g_sums2[b*2+1], sq); }
    }
}

// ---------- HMMA flash attention (unchanged from passing R15) ----------
#define KVB (64*ALD*2)

__global__ void __launch_bounds__(256) attn_mma(float* __restrict__ outp)
{
    extern __shared__ __nv_bfloat16 smb[];
    const uint32_t uQH = s2u(smb);
    const uint32_t uQL = uQH + 128*ALD*2;
    const uint32_t uKV = uQL + 128*ALD*2;

    int it = blockIdx.x, h = blockIdx.y, b = blockIdx.z;
    int tid = threadIdx.x, lane = tid & 31, w = tid >> 5;
    int g = lane >> 2, tq = lane & 3;
    int q0 = w * 16;

    const int lrow = lane & 7, lt = lane >> 3;
    const uint32_t a_off = (uint32_t)((q0 + ((lt & 1) << 3) + lrow) * (ALD*2) + (lt >> 1) * 16);
    const uint32_t b_off = (uint32_t)((((lt >> 1) << 3) + lrow) * (ALD*2) + (lt & 1) * 16);

    {
        int q = tid >> 1, seg = (tid & 1) * 32;
        const __nv_bfloat16* sH = g_qkH + ((size_t)b*NSP + it*128 + q)*512 + h*64 + seg;
        const __nv_bfloat16* sL = g_qkL + ((size_t)b*NSP + it*128 + q)*512 + h*64 + seg;
        uint32_t dH = uQH + (uint32_t)(q*ALD + seg)*2;
        uint32_t dL = uQL + (uint32_t)(q*ALD + seg)*2;
        CP16(dH, sH); CP16(dH+16, sH+8); CP16(dH+32, sH+16); CP16(dH+48, sH+24);
        CP16(dL, sL); CP16(dL+16, sL+8); CP16(dL+32, sL+16); CP16(dL+48, sL+24);
    }
    auto stageKV = [&](int kt, int bi) {
        uint32_t base = uKV + (uint32_t)bi*4*KVB;
        {
            int key = tid >> 2, sg = (tid & 3) * 16;
            const __nv_bfloat16* sH = g_qkH + ((size_t)b*NSP + kt*64 + key)*512 + 256 + h*64 + sg;
            const __nv_bfloat16* sL = g_qkL + ((size_t)b*NSP + kt*64 + key)*512 + 256 + h*64 + sg;
            uint32_t dH = base + (uint32_t)(key*ALD + sg)*2;
            uint32_t dL = base + KVB + (uint32_t)(key*ALD + sg)*2;
            CP16(dH, sH); CP16(dH+16, sH+8);
            CP16(dL, sL); CP16(dL+16, sL+8);
        }
        {
            int d = tid >> 2, sg = (tid & 3) * 16;
            const __nv_bfloat16* sH = g_vH + ((size_t)b*CCH + h*64 + d)*NSP + kt*64 + sg;
            const __nv_bfloat16* sL = g_vL + ((size_t)b*CCH + h*64 + d)*NSP + kt*64 + sg;
            uint32_t dH = base + 2*KVB + (uint32_t)(d*ALD + sg)*2;
            uint32_t dL = base + 3*KVB + (uint32_t)(d*ALD + sg)*2;
            CP16(dH, sH); CP16(dH+16, sH+8);
            CP16(dL, sL); CP16(dL+16, sL+8);
        }
        asm volatile("cp.async.commit_group;" ::: "memory");
    };

    stageKV(0, 0);

    float m0 = -1e30f, m1 = -1e30f, l0 = 0.f, l1 = 0.f;
    float oacc[8][4] = {};

    for (int kt = 0; kt < 16; kt++) {
        int bi = kt & 1;
        if (kt + 1 < 16) {
            stageKV(kt + 1, bi ^ 1);
            asm volatile("cp.async.wait_group 1;" ::: "memory");
        } else {
            asm volatile("cp.async.wait_group 0;" ::: "memory");
        }
        __syncthreads();

        uint32_t uKH = uKV + (uint32_t)bi*4*KVB;
        uint32_t uKL = uKH + KVB, uVH = uKH + 2*KVB, uVL = uKH + 3*KVB;

        float sacc[8][4] = {};
        #pragma unroll
        for (int kc = 0; kc < 4; kc++) {
            uint32_t aH[4], aL[4];
            ldsm4(aH[0], aH[1], aH[2], aH[3], uQH + a_off + kc*32);
            ldsm4(aL[0], aL[1], aL[2], aL[3], uQL + a_off + kc*32);
            #pragma unroll
            for (int p = 0; p < 4; p++) {
                uint32_t h0, h1, h2, h3, x0, x1, x2, x3;
                ldsm4(h0, h1, h2, h3, uKH + b_off + p*16*(ALD*2) + kc*32);
                ldsm4(x0, x1, x2, x3, uKL + b_off + p*16*(ALD*2) + kc*32);
                MMA_B16(sacc[2*p  ], aH, h0, h1);
                MMA_B16(sacc[2*p  ], aH, x0, x1);
                MMA_B16(sacc[2*p  ], aL, h0, h1);
                MMA_B16(sacc[2*p+1], aH, h2, h3);
                MMA_B16(sacc[2*p+1], aH, x2, x3);
                MMA_B16(sacc[2*p+1], aL, h2, h3);
            }
        }

        float rm0 = -1e30f, rm1 = -1e30f;
        #pragma unroll
        for (int nf = 0; nf < 8; nf++) {
            rm0 = fmaxf(rm0, fmaxf(sacc[nf][0], sacc[nf][1]));
            rm1 = fmaxf(rm1, fmaxf(sacc[nf][2], sacc[nf][3]));
        }
        rm0 = fmaxf(rm0, __shfl_xor_sync(0xffffffffu, rm0, 1));
        rm0 = fmaxf(rm0, __shfl_xor_sync(0xffffffffu, rm0, 2));
        rm1 = fmaxf(rm1, __shfl_xor_sync(0xffffffffu, rm1, 1));
        rm1 = fmaxf(rm1, __shfl_xor_sync(0xffffffffu, rm1, 2));
        float mn0 = fmaxf(m0, rm0), mn1 = fmaxf(m1, rm1);
        float al0 = __expf(m0 - mn0), al1 = __expf(m1 - mn1);
        m0 = mn0; m1 = mn1;
        float ls0 = 0.f, ls1 = 0.f;
        #pragma unroll
        for (int nf = 0; nf < 8; nf++) {
            sacc[nf][0] = __expf(sacc[nf][0] - mn0);
            sacc[nf][1] = __expf(sacc[nf][1] - mn0);
            sacc[nf][2] = __expf(sacc[nf][2] - mn1);
            sacc[nf][3] = __expf(sacc[nf][3] - mn1);
            ls0 += sacc[nf][0] + sacc[nf][1];
            ls1 += sacc[nf][2] + sacc[nf][3];
        }
        ls0 += __shfl_xor_sync(0xffffffffu, ls0, 1);
        ls0 += __shfl_xor_sync(0xffffffffu, ls0, 2);
        ls1 += __shfl_xor_sync(0xffffffffu, ls1, 1);
        ls1 += __shfl_xor_sync(0xffffffffu, ls1, 2);
        l0 = l0 * al0 + ls0;
        l1 = l1 * al1 + ls1;
        #pragma unroll
        for (int nf = 0; nf < 8; nf++) {
            oacc[nf][0] *= al0; oacc[nf][1] *= al0;
            oacc[nf][2] *= al1; oacc[nf][3] *= al1;
        }

        uint32_t pH[4][4], pL[4][4];
        #pragma unroll
        for (int c = 0; c < 4; c++) {
            pack2(sacc[2*c  ][0], sacc[2*c  ][1], pH[c][0], pL[c][0]);
            pack2(sacc[2*c  ][2], sacc[2*c  ][3], pH[c][1], pL[c][1]);
            pack2(sacc[2*c+1][0], sacc[2*c+1][1], pH[c][2], pL[c][2]);
            pack2(sacc[2*c+1][2], sacc[2*c+1][3], pH[c][3], pL[c][3]);
        }

        #pragma unroll
        for (int c = 0; c < 4; c++) {
            #pragma unroll
            for (int p = 0; p < 4; p++) {
                uint32_t h0, h1, h2, h3, x0, x1, x2, x3;
                ldsm4(h0, h1, h2, h3, uVH + b_off + p*16*(ALD*2) + c*32);
                ldsm4(x0, x1, x2, x3, uVL + b_off + p*16*(ALD*2) + c*32);
                MMA_B16(oacc[2*p  ], pH[c], h0, h1);
                MMA_B16(oacc[2*p  ], pH[c], x0, x1);
                MMA_B16(oacc[2*p  ], pL[c], h0, h1);
                MMA_B16(oacc[2*p+1], pH[c], h2, h3);
                MMA_B16(oacc[2*p+1], pH[c], x2, x3);
                MMA_B16(oacc[2*p+1], pL[c], h2, h3);
            }
        }
        __syncthreads();
    }

    float inv0 = 1.f / l0, inv1 = 1.f / l1;
    float* OS = (float*)smb;
    #pragma unroll
    for (int nf = 0; nf < 8; nf++) {
        int d = nf*8 + 2*tq;
        OS[(d  )*128 + q0 + g    ] = oacc[nf][0] * inv0;
        OS[(d+1)*128 + q0 + g    ] = oacc[nf][1] * inv0;
        OS[(d  )*128 + q0 + g + 8] = oacc[nf][2] * inv1;
        OS[(d+1)*128 + q0 + g + 8] = oacc[nf][3] * inv1;
    }
    __syncthreads();
    {
        int d = tid >> 2, q32 = (tid & 3) * 32;
        float* ob = outp + ((size_t)b*CCH + h*DKD + d)*NSP + it*128 + q32;
        #pragma unroll
        for (int j = 0; j < 8; j++)
            *(float4*)(ob + j*4) = *(const float4*)&OS[d*128 + q32 + j*4];
    }
}

// ---------- launch ----------
#define ATTN_SMEM ((2*128 + 8*64)*ALD*2)
#define GEMM_SMEM (4*128*ALD*2)

extern "C" void kernel_launch(void* const* d_in, const int* in_sizes, int n_in,
                              void* d_out, int out_size) {
    const float* x     = (const float*)d_in[0];
    const float* qkv_w = (const float*)d_in[1];
    const float* uh_w  = (const float*)d_in[2];
    const float* uh_b  = (const float*)d_in[3];
    const float* n1_w  = (const float*)d_in[4];
    const float* n1_b  = (const float*)d_in[5];
    const float* n2_w  = (const float*)d_in[6];
    const float* n2_b  = (const float*)d_in[7];
    const float* f1_w  = (const float*)d_in[8];
    const float* f1_b  = (const float*)d_in[9];
    const float* f2_w  = (const float*)d_in[10];
    const float* f2_b  = (const float*)d_in[11];
    const float* g_at  = (const float*)d_in[12];
    const float* g_ff  = (const float*)d_in[13];
    float* out = (float*)d_out;

    float *attn_buf, *x2_buf;
    __nv_bfloat16 *wH, *wL, *aH, *aL, *h1H, *h1L;
    cudaGetSymbolAddress((void**)&attn_buf, g_attn);
    cudaGetSymbolAddress((void**)&x2_buf,   g_x2);
    cudaGetSymbolAddress((void**)&wH, g_wH);
    cudaGetSymbolAddress((void**)&wL, g_wL);
    cudaGetSymbolAddress((void**)&aH, g_aH);
    cudaGetSymbolAddress((void**)&aL, g_aL);
    cudaGetSymbolAddress((void**)&h1H, g_h1H);
    cudaGetSymbolAddress((void**)&h1L, g_h1L);

    cudaFuncSetAttribute(attn_mma, cudaFuncAttributeMaxDynamicSharedMemorySize, ATTN_SMEM);
    cudaFuncSetAttribute(gemm_cp<256,0>,  cudaFuncAttributeMaxDynamicSharedMemorySize, GEMM_SMEM);
    cudaFuncSetAttribute(gemm_cp<256,4>,  cudaFuncAttributeMaxDynamicSharedMemorySize, GEMM_SMEM);
    cudaFuncSetAttribute(gemm_cp<1024,3>, cudaFuncAttributeMaxDynamicSharedMemorySize, GEMM_SMEM);
    cudaFuncSetAttribute(gemm_mma<256,1>, cudaFuncAttributeMaxDynamicSharedMemorySize, GEMM_SMEM);

    zero_stats_kernel<<<1, 32>>>();
    gn_stats_kernel<<<dim3(32, BSZ), 256>>>(x);
    convert_w_all<<<1536, 256>>>(qkv_w, uh_w, f1_w, f2_w);

    // GN1(x) -> token-major split
    prep_act<1><<<dim3(32, 8, BSZ), 256>>>(x, n1_w, n1_b);

    // qkv = qkv_w @ GN1(x) -> split Q/K token-major + V channel-major (all cp.async)
    gemm_cp<256,0><<<dim3(8,6,BSZ), 256, GEMM_SMEM>>>(
        wH + W_QKV, wL + W_QKV, aH, aL, nullptr, nullptr, nullptr, nullptr);

    attn_mma<<<dim3(8, NHH, BSZ), 256, ATTN_SMEM>>>(attn_buf);

    // x2 = x + g_at*(uh_w@attn + uh_b), + GN2 stats (legacy staging; attn is fp32)
    gemm_mma<256,1><<<dim3(8,2,BSZ), 256, GEMM_SMEM>>>(
        attn_buf, wH + W_UH, wL + W_UH, uh_b, x, g_at, x2_buf);

    // GN2(x2) -> token-major split (reuses g_aH/aL)
    prep_act<2><<<dim3(32, 8, BSZ), 256>>>(x2_buf, n2_w, n2_b);

    // h1 = silu(f1_w @ GN2(x2) + f1_b) -> token-major split h1
    gemm_cp<256,4><<<dim3(8,8,BSZ), 256, GEMM_SMEM>>>(
        wH + W_F1, wL + W_F1, aH, aL, f1_b, nullptr, nullptr, nullptr);

    // out = x2 + g_ff*(f2_w@h1 + f2_b)
    gemm_cp<1024,3><<<dim3(8,2,BSZ), 256, GEMM_SMEM>>>(
        wH + W_F2, wL + W_F2, h1H, h1L, f2_b, x2_buf, g_ff, out);
}

// round 17
// speedup vs baseline: 1.0391x; 1.0391x over previous
#include <cuda_runtime.h>
#include <cuda_bf16.h>
#include <math.h>
#include <stdint.h>

#define BSZ 8
#define CCH 256
#define NSP 1024
#define NHH 4
#define DKD 64
#define CNT (CCH*NSP)

__device__ float g_sums1[2*BSZ];
__device__ float g_sums2[2*BSZ];
__device__ float g_attn[(size_t)BSZ*CCH*NSP];
__device__ float g_x2  [(size_t)BSZ*CCH*NSP];

__device__ __nv_bfloat16 g_qkH[(size_t)BSZ*NSP*512];
__device__ __nv_bfloat16 g_qkL[(size_t)BSZ*NSP*512];
__device__ __nv_bfloat16 g_vH [(size_t)BSZ*CCH*NSP];
__device__ __nv_bfloat16 g_vL [(size_t)BSZ*CCH*NSP];
__device__ __nv_bfloat16 g_aH[(size_t)BSZ*NSP*CCH];
__device__ __nv_bfloat16 g_aL[(size_t)BSZ*NSP*CCH];
__device__ __nv_bfloat16 g_h1H[(size_t)BSZ*NSP*1024];
__device__ __nv_bfloat16 g_h1L[(size_t)BSZ*NSP*1024];

#define W_QKV 0
#define W_UH  196608
#define W_F1  262144
#define W_F2  524288
__device__ __nv_bfloat16 g_wH[786432];
__device__ __nv_bfloat16 g_wL[786432];

// ---------- reductions / stats ----------
__device__ __forceinline__ void block_reduce2(float& s, float& s2) {
    #pragma unroll
    for (int o = 16; o; o >>= 1) {
        s  += __shfl_xor_sync(0xffffffffu, s,  o);
        s2 += __shfl_xor_sync(0xffffffffu, s2, o);
    }
    __shared__ float sh0[8], sh1[8];
    int w = threadIdx.x >> 5, l = threadIdx.x & 31;
    if (l == 0) { sh0[w] = s; sh1[w] = s2; }
    __syncthreads();
    if (w == 0) {
        s  = (l < 8) ? sh0[l] : 0.f;
        s2 = (l < 8) ? sh1[l] : 0.f;
        #pragma unroll
        for (int o = 4; o; o >>= 1) {
            s  += __shfl_xor_sync(0xffffffffu, s,  o);
            s2 += __shfl_xor_sync(0xffffffffu, s2, o);
        }
    }
}

__global__ void zero_stats_kernel() {
    int t = threadIdx.x;
    if (t < 2*BSZ) { g_sums1[t] = 0.f; g_sums2[t] = 0.f; }
}

__global__ void gn_stats_kernel(const float* __restrict__ x) {
    int b = blockIdx.y;
    const float* xb = x + (size_t)b * CNT;
    int base = blockIdx.x * (CNT / 32);
    float s = 0.f, s2 = 0.f;
    for (int i = threadIdx.x; i < CNT/32; i += 256) {
        float v = xb[base + i];
        s += v; s2 += v*v;
    }
    block_reduce2(s, s2);
    if (threadIdx.x == 0) {
        atomicAdd(&g_sums1[b*2],   s);
        atomicAdd(&g_sums1[b*2+1], s2);
    }
}

// ---------- helpers ----------
#define MMA_B16(c, a, b0, b1) \
  asm volatile("mma.sync.aligned.m16n8k16.row.col.f32.bf16.bf16.f32 " \
    "{%0,%1,%2,%3}, {%4,%5,%6,%7}, {%8,%9}, {%0,%1,%2,%3};" \
    : "+f"((c)[0]),"+f"((c)[1]),"+f"((c)[2]),"+f"((c)[3]) \
    : "r"((a)[0]),"r"((a)[1]),"r"((a)[2]),"r"((a)[3]), "r"(b0),"r"(b1))

__device__ __forceinline__ void ldsm4(uint32_t& r0, uint32_t& r1, uint32_t& r2,
                                      uint32_t& r3, uint32_t addr) {
    asm volatile("ldmatrix.sync.aligned.m8n8.x4.shared.b16 {%0,%1,%2,%3}, [%4];"
        : "=r"(r0), "=r"(r1), "=r"(r2), "=r"(r3) : "r"(addr));
}
__device__ __forceinline__ uint32_t s2u(const void* p) {
    return (uint32_t)__cvta_generic_to_shared(p);
}
__device__ __forceinline__ void split_bf16(float v, __nv_bfloat16& h, __nv_bfloat16& l) {
    h = __float2bfloat16(v);
    l = __float2bfloat16(v - __bfloat162float(h));
}
__device__ __forceinline__ void pack2(float a, float b, uint32_t& h, uint32_t& l) {
    __nv_bfloat162 hb = __floats2bfloat162_rn(a, b);
    float ra = a - __bfloat162float(hb.x);
    float rb = b - __bfloat162float(hb.y);
    __nv_bfloat162 lb = __floats2bfloat162_rn(ra, rb);
    h = *(uint32_t*)&hb; l = *(uint32_t*)&lb;
}
#define CP16(dst, src) \
    asm volatile("cp.async.cg.shared.global [%0], [%1], 16;" :: "r"(dst), "l"(src) : "memory")

__global__ void convert_w_all(const float* __restrict__ qkv_w, const float* __restrict__ uh_w,
                              const float* __restrict__ f1_w, const float* __restrict__ f2_w) {
    int i = blockIdx.x * blockDim.x + threadIdx.x;
    if (i >= 393216) return;
    const float* src; int li, base;
    if      (i <  98304) { src = qkv_w; li = i;          base = W_QKV; }
    else if (i < 131072) { src = uh_w;  li = i -  98304; base = W_UH;  }
    else if (i < 262144) { src = f1_w;  li = i - 131072; base = W_F1;  }
    else                 { src = f2_w;  li = i - 262144; base = W_F2;  }
    float2 f = *(const float2*)(src + 2*li);
    uint32_t H, L;
    pack2(f.x, f.y, H, L);
    *(uint32_t*)(g_wH + base + 2*li) = H;
    *(uint32_t*)(g_wL + base + 2*li) = L;
}

// GN + split + transpose: src [b][256][1024] fp32 -> g_aH/g_aL [b][tok][256]
template<int NORM>
__global__ void prep_act(const float* __restrict__ src,
                         const float* __restrict__ gw, const float* __restrict__ gb) {
    __shared__ float tile[32][33];
    int b = blockIdx.z;
    int c0 = blockIdx.y * 32, t0v = blockIdx.x * 32;
    int tx = threadIdx.x & 31, ty = threadIdx.x >> 5;
    const float* sums = (NORM == 1) ? g_sums1 : g_sums2;
    float mean = sums[b*2] * (1.f/CNT);
    float rstd = rsqrtf(sums[b*2+1] * (1.f/CNT) - mean*mean + 1e-5f);
    #pragma unroll
    for (int r = 0; r < 4; r++) {
        int ch = c0 + ty + 8*r;
        float gwc = gw[ch]*rstd, gbc = gb[ch] - mean*gwc;
        tile[ty + 8*r][tx] = src[((size_t)b*CCH + ch)*NSP + t0v + tx] * gwc + gbc;
    }
    __syncthreads();
    #pragma unroll
    for (int r = 0; r < 4; r++) {
        int tok = t0v + ty + 8*r;
        float v = tile[tx][ty + 8*r];
        __nv_bfloat16 h, l; split_bf16(v, h, l);
        size_t o = ((size_t)b*NSP + tok)*CCH + c0 + tx;
        g_aH[o] = h; g_aL[o] = l;
    }
}

#define ALD 72        // attention / legacy gemm row stride
#define ALD2 40       // pipelined gemm_cp row stride (32 k + pad)
#define TSB2 (128*ALD2*2)

// ---------- gemm_cp: all-cp.async, K-chunk 32, double-buffered (2 CTA/SM) ----------
// EPI: 0 qkv-split-out, 3 bias+resid*g (final), 4 bias+silu -> token-major split h1
template<int KD, int EPI>
__global__ void __launch_bounds__(256) gemm_cp(
    const __nv_bfloat16* __restrict__ WH, const __nv_bfloat16* __restrict__ WL,
    const __nv_bfloat16* __restrict__ AH, const __nv_bfloat16* __restrict__ AL,
    const float* __restrict__ bias, const float* __restrict__ resid,
    const float* __restrict__ gamma, float* __restrict__ out)
{
    extern __shared__ __nv_bfloat16 smg[];
    const uint32_t uS = s2u(smg);   // [bi][WH, WL, AH, AL] tiles of 128 x ALD2

    int tid = threadIdx.x, lane = tid & 31, w = tid >> 5;
    int wm = w & 3, wn = w >> 2;
    int t0 = blockIdx.x * 128, m0 = blockIdx.y * 128, b = blockIdx.z;

    float acc[2][8][4] = {};
    const int g = lane >> 2, tq = lane & 3;
    const int lrow = lane & 7, lt = lane >> 3;
    const uint32_t a_off = (uint32_t)((wm*32 + ((lt & 1) << 3) + lrow) * (ALD2*2) + (lt >> 1) * 16);
    const uint32_t b_off = (uint32_t)(((wn*64) + ((lt >> 1) << 3) + lrow) * (ALD2*2) + (lt & 1) * 16);

    const int sm_m = tid >> 1, sm_kh = (tid & 1) * 16;   // halfword offset 0/16
    const uint32_t soff = (uint32_t)(sm_m*ALD2 + sm_kh)*2;
    const __nv_bfloat16* wHb = WH + (size_t)(m0 + sm_m)*KD + sm_kh;
    const __nv_bfloat16* wLb = WL + (size_t)(m0 + sm_m)*KD + sm_kh;
    const __nv_bfloat16* aHb = AH + ((size_t)b*NSP + t0 + sm_m)*KD + sm_kh;
    const __nv_bfloat16* aLb = AL + ((size_t)b*NSP + t0 + sm_m)*KD + sm_kh;

    auto stage = [&](int c, int bi) {
        int kc = c * 32;
        uint32_t base = uS + (uint32_t)bi*4*TSB2;
        const __nv_bfloat16* pH = wHb + kc;
        const __nv_bfloat16* pL = wLb + kc;
        const __nv_bfloat16* qH = aHb + kc;
        const __nv_bfloat16* qL = aLb + kc;
        uint32_t d0 = base + soff;
        uint32_t d1 = base + TSB2 + soff;
        uint32_t d2 = base + 2*TSB2 + soff;
        uint32_t d3 = base + 3*TSB2 + soff;
        CP16(d0, pH); CP16(d0+16, pH+8);
        CP16(d1, pL); CP16(d1+16, pL+8);
        CP16(d2, qH); CP16(d2+16, qH+8);
        CP16(d3, qL); CP16(d3+16, qL+8);
        asm volatile("cp.async.commit_group;" ::: "memory");
    };

    constexpr int NCH = KD/32;
    stage(0, 0);
    for (int c = 0; c < NCH; c++) {
        int bi = c & 1;
        if (c + 1 < NCH) {
            stage(c + 1, bi ^ 1);
            asm volatile("cp.async.wait_group 1;" ::: "memory");
        } else {
            asm volatile("cp.async.wait_group 0;" ::: "memory");
        }
        __syncthreads();

        uint32_t uAHb = uS + (uint32_t)bi*4*TSB2, uALb = uAHb + TSB2;
        uint32_t uBHb = uALb + TSB2,              uBLb = uBHb + TSB2;
        #pragma unroll
        for (int k4 = 0; k4 < 2; k4++) {
            uint32_t aHf[2][4], aLf[2][4];
            #pragma unroll
            for (int mf = 0; mf < 2; mf++) {
                ldsm4(aHf[mf][0], aHf[mf][1], aHf[mf][2], aHf[mf][3],
                      uAHb + a_off + mf*16*(ALD2*2) + k4*32);
                ldsm4(aLf[mf][0], aLf[mf][1], aLf[mf][2], aLf[mf][3],
                      uALb + a_off + mf*16*(ALD2*2) + k4*32);
            }
            #pragma unroll
            for (int p = 0; p < 4; p++) {
                uint32_t h0, h1, h2, h3, x0, x1, x2, x3;
                ldsm4(h0, h1, h2, h3, uBHb + b_off + p*16*(ALD2*2) + k4*32);
                ldsm4(x0, x1, x2, x3, uBLb + b_off + p*16*(ALD2*2) + k4*32);
                #pragma unroll
                for (int mf = 0; mf < 2; mf++) {
                    MMA_B16(acc[mf][2*p  ], aHf[mf], h0, h1);
                    MMA_B16(acc[mf][2*p  ], aHf[mf], x0, x1);
                    MMA_B16(acc[mf][2*p  ], aLf[mf], h0, h1);
                    MMA_B16(acc[mf][2*p+1], aHf[mf], h2, h3);
                    MMA_B16(acc[mf][2*p+1], aHf[mf], x2, x3);
                    MMA_B16(acc[mf][2*p+1], aLf[mf], h2, h3);
                }
            }
        }
        __syncthreads();
    }

    if (EPI == 0) {
        if (m0 < 512) {
            __nv_bfloat16* EH = smg;             // [128 tok][136]
            __nv_bfloat16* EL = smg + 128*136;
            float scale = (m0 < 256) ? 0.125f : 1.f;
            #pragma unroll
            for (int mf = 0; mf < 2; mf++) {
                int chl = wm*32 + mf*16 + g;
                #pragma unroll
                for (int nf = 0; nf < 8; nf++) {
                    int tokl = wn*64 + nf*8 + tq*2;
                    __nv_bfloat16 h, l;
                    split_bf16(acc[mf][nf][0]*scale, h, l);
                    EH[ tokl   *136 + chl    ] = h; EL[ tokl   *136 + chl    ] = l;
                    split_bf16(acc[mf][nf][1]*scale, h, l);
                    EH[(tokl+1)*136 + chl    ] = h; EL[(tokl+1)*136 + chl    ] = l;
                    split_bf16(acc[mf][nf][2]*scale, h, l);
                    EH[ tokl   *136 + chl + 8] = h; EL[ tokl   *136 + chl + 8] = l;
                    split_bf16(acc[mf][nf][3]*scale, h, l);
                    EH[(tokl+1)*136 + chl + 8] = h; EL[(tokl+1)*136 + chl + 8] = l;
                }
            }
            __syncthreads();
            int tok = tid >> 1, half = (tid & 1) * 64;
            size_t o = ((size_t)b*NSP + t0 + tok)*512 + m0 + half;
            #pragma unroll
            for (int j = 0; j < 8; j++) {
                *(uint4*)(g_qkH + o + j*8) = *(const uint4*)&EH[tok*136 + half + j*8];
                *(uint4*)(g_qkL + o + j*8) = *(const uint4*)&EL[tok*136 + half + j*8];
            }
        } else {
            #pragma unroll
            for (int mf = 0; mf < 2; mf++) {
                int row = (m0 - 512) + wm*32 + mf*16 + g;
                #pragma unroll
                for (int nf = 0; nf < 8; nf++) {
                    int col = t0 + wn*64 + nf*8 + tq*2;
                    uint32_t H, L;
                    pack2(acc[mf][nf][0], acc[mf][nf][1], H, L);
                    size_t i0 = ((size_t)b*CCH + row)*NSP + col;
                    *(uint32_t*)(g_vH + i0) = H; *(uint32_t*)(g_vL + i0) = L;
                    pack2(acc[mf][nf][2], acc[mf][nf][3], H, L);
                    size_t i8 = ((size_t)b*CCH + row + 8)*NSP + col;
                    *(uint32_t*)(g_vH + i8) = H; *(uint32_t*)(g_vL + i8) = L;
                }
            }
        }
        return;
    }

    if (EPI == 4) {
        __nv_bfloat16* EH = smg;
        __nv_bfloat16* EL = smg + 128*136;
        #pragma unroll
        for (int mf = 0; mf < 2; mf++) {
            int chl = wm*32 + mf*16 + g;
            float b0 = bias[m0 + chl], b8 = bias[m0 + chl + 8];
            #pragma unroll
            for (int nf = 0; nf < 8; nf++) {
                int tokl = wn*64 + nf*8 + tq*2;
                float v0 = acc[mf][nf][0] + b0; v0 = v0 / (1.f + __expf(-v0));
                float v1 = acc[mf][nf][1] + b0; v1 = v1 / (1.f + __expf(-v1));
                float v2 = acc[mf][nf][2] + b8; v2 = v2 / (1.f + __expf(-v2));
                float v3 = acc[mf][nf][3] + b8; v3 = v3 / (1.f + __expf(-v3));
                __nv_bfloat16 h, l;
                split_bf16(v0, h, l);
                EH[ tokl   *136 + chl    ] = h; EL[ tokl   *136 + chl    ] = l;
                split_bf16(v1, h, l);
                EH[(tokl+1)*136 + chl    ] = h; EL[(tokl+1)*136 + chl    ] = l;
                split_bf16(v2, h, l);
                EH[ tokl   *136 + chl + 8] = h; EL[ tokl   *136 + chl + 8] = l;
                split_bf16(v3, h, l);
                EH[(tokl+1)*136 + chl + 8] = h; EL[(tokl+1)*136 + chl + 8] = l;
            }
        }
        __syncthreads();
        int tok = tid >> 1, half = (tid & 1) * 64;
        size_t o = ((size_t)b*NSP + t0 + tok)*1024 + m0 + half;
        #pragma unroll
        for (int j = 0; j < 8; j++) {
            *(uint4*)(g_h1H + o + j*8) = *(const uint4*)&EH[tok*136 + half + j*8];
            *(uint4*)(g_h1L + o + j*8) = *(const uint4*)&EL[tok*136 + half + j*8];
        }
        return;
    }

    // EPI == 3
    float gm = gamma[0];
    #pragma unroll
    for (int mf = 0; mf < 2; mf++) {
        int row = m0 + wm*32 + mf*16 + g;
        float bi0 = bias[row], bi8 = bias[row + 8];
        #pragma unroll
        for (int nf = 0; nf < 8; nf++) {
            int col = t0 + wn*64 + nf*8 + tq*2;
            size_t i0 = ((size_t)b*CCH + row    )*NSP + col;
            size_t i8 = ((size_t)b*CCH + row + 8)*NSP + col;
            float2 r0 = *(const float2*)(resid + i0);
            float2 r8 = *(const float2*)(resid + i8);
            float v00 = r0.x + gm*(acc[mf][nf][0] + bi0);
            float v01 = r0.y + gm*(acc[mf][nf][1] + bi0);
            float v10 = r8.x + gm*(acc[mf][nf][2] + bi8);
            float v11 = r8.y + gm*(acc[mf][nf][3] + bi8);
            *(float2*)(out + i0) = make_float2(v00, v01);
            *(float2*)(out + i8) = make_float2(v10, v11);
        }
    }
}

// ---------- gemm_mma (legacy transpose-convert path; uh only) ----------
template<int K, int EPI>
__global__ void __launch_bounds__(256) gemm_mma(
    const float* __restrict__ Act,
    const __nv_bfloat16* __restrict__ WH, const __nv_bfloat16* __restrict__ WL,
    const float* __restrict__ bias, const float* __restrict__ resid,
    const float* __restrict__ gamma, float* __restrict__ out)
{
    extern __shared__ __nv_bfloat16 smg[];
    __nv_bfloat16* AsH = smg;
    __nv_bfloat16* AsL = AsH + 128*ALD;
    __nv_bfloat16* BsH = AsL + 128*ALD;
    __nv_bfloat16* BsL = BsH + 128*ALD;

    int tid = threadIdx.x, lane = tid & 31, w = tid >> 5;
    int wm = w & 3, wn = w >> 2;
    int t0 = blockIdx.x * 128, m0 = blockIdx.y * 128, b = blockIdx.z;

    float acc[2][8][4] = {};
    const int g = lane >> 2, tq = lane & 3;
    const int lrow = lane & 7, lt = lane >> 3;
    const uint32_t a_off = (uint32_t)((wm*32 + ((lt & 1) << 3) + lrow) * (ALD*2) + (lt >> 1) * 16);
    const uint32_t b_off = (uint32_t)(((wn*64) + ((lt >> 1) << 3) + lrow) * (ALD*2) + (lt & 1) * 16);
    const uint32_t uAH = s2u(AsH), uAL = s2u(AsL);
    const uint32_t uBH = s2u(BsH), uBL = s2u(BsL);

    const int sm_m = tid >> 1, sm_kh = (tid & 1) * 32;
    const int sdp = tid & 31, stg = tid >> 5;

    for (int c = 0; c < K/64; c++) {
        int kc = c * 64;
        {
            const __nv_bfloat16* pH = WH + (size_t)(m0 + sm_m)*K + kc + sm_kh;
            const __nv_bfloat16* pL = WL + (size_t)(m0 + sm_m)*K + kc + sm_kh;
            uint32_t dH = uAH + (uint32_t)(sm_m*ALD + sm_kh)*2;
            uint32_t dL = uAL + (uint32_t)(sm_m*ALD + sm_kh)*2;
            CP16(dH, pH); CP16(dH+16, pH+8); CP16(dH+32, pH+16); CP16(dH+48, pH+24);
            CP16(dL, pL); CP16(dL+16, pL+8); CP16(dL+32, pL+16); CP16(dL+48, pL+24);
            asm volatile("cp.async.commit_group;" ::: "memory");
        }
        {
            int ch = kc + 2*sdp;
            const float* p0 = Act + ((size_t)b*K + ch)*NSP + t0 + stg*16;
            const float* p1 = p0 + NSP;
            #pragma unroll
            for (int qd = 0; qd < 4; qd++) {
                float4 fa = *(const float4*)(p0 + qd*4);
                float4 fb = *(const float4*)(p1 + qd*4);
                float va[4] = {fa.x, fa.y, fa.z, fa.w};
                float vbb[4] = {fb.x, fb.y, fb.z, fb.w};
                #pragma unroll
                for (int e = 0; e < 4; e++) {
                    int tok = stg*16 + qd*4 + e;
                    uint32_t H, L;
                    pack2(va[e], vbb[e], H, L);
                    *(uint32_t*)&BsH[tok*ALD + 2*sdp] = H;
                    *(uint32_t*)&BsL[tok*ALD + 2*sdp] = L;
                }
            }
        }
        asm volatile("cp.async.wait_group 0;" ::: "memory");
        __syncthreads();

        #pragma unroll
        for (int k4 = 0; k4 < 4; k4++) {
            uint32_t aH[2][4], aL[2][4];
            #pragma unroll
            for (int mf = 0; mf < 2; mf++) {
                ldsm4(aH[mf][0], aH[mf][1], aH[mf][2], aH[mf][3],
                      uAH + a_off + mf*16*(ALD*2) + k4*32);
                ldsm4(aL[mf][0], aL[mf][1], aL[mf][2], aL[mf][3],
                      uAL + a_off + mf*16*(ALD*2) + k4*32);
            }
            #pragma unroll
            for (int p = 0; p < 4; p++) {
                uint32_t h0, h1, h2, h3, x0, x1, x2, x3;
                ldsm4(h0, h1, h2, h3, uBH + b_off + p*16*(ALD*2) + k4*32);
                ldsm4(x0, x1, x2, x3, uBL + b_off + p*16*(ALD*2) + k4*32);
                #pragma unroll
                for (int mf = 0; mf < 2; mf++) {
                    MMA_B16(acc[mf][2*p  ], aH[mf], h0, h1);
                    MMA_B16(acc[mf][2*p  ], aH[mf], x0, x1);
                    MMA_B16(acc[mf][2*p  ], aL[mf], h0, h1);
                    MMA_B16(acc[mf][2*p+1], aH[mf], h2, h3);
                    MMA_B16(acc[mf][2*p+1], aH[mf], x2, x3);
                    MMA_B16(acc[mf][2*p+1], aL[mf], h2, h3);
                }
            }
        }
        __syncthreads();
    }

    float gm = gamma[0];
    float s1 = 0.f, sq = 0.f;
    #pragma unroll
    for (int mf = 0; mf < 2; mf++) {
        int row = m0 + wm*32 + mf*16 + g;
        float bi0 = bias[row], bi8 = bias[row + 8];
        #pragma unroll
        for (int nf = 0; nf < 8; nf++) {
            int col = t0 + wn*64 + nf*8 + tq*2;
            float v00 = acc[mf][nf][0] + bi0;
            float v01 = acc[mf][nf][1] + bi0;
            float v10 = acc[mf][nf][2] + bi8;
            float v11 = acc[mf][nf][3] + bi8;
            size_t i0 = ((size_t)b*CCH + row    )*NSP + col;
            size_t i8 = ((size_t)b*CCH + row + 8)*NSP + col;
            float2 r0 = *(const float2*)(resid + i0);
            float2 r8 = *(const float2*)(resid + i8);
            v00 = r0.x + gm*v00;  v01 = r0.y + gm*v01;
            v10 = r8.x + gm*v10;  v11 = r8.y + gm*v11;
            if (EPI == 1) {
                s1 += v00+v01+v10+v11;
                sq += v00*v00 + v01*v01 + v10*v10 + v11*v11;
            }
            *(float2*)(out + i0) = make_float2(v00, v01);
            *(float2*)(out + i8) = make_float2(v10, v11);
        }
    }
    if (EPI == 1) {
        block_reduce2(s1, sq);
        if (tid == 0) { atomicAdd(&g_sums2[b*2], s1); atomicAdd(&g_sums2[b*2+1], sq); }
    }
}

// ---------- HMMA flash attention (unchanged from passing R15) ----------
#define KVB (64*ALD*2)

__global__ void __launch_bounds__(256) attn_mma(float* __restrict__ outp)
{
    extern __shared__ __nv_bfloat16 smb[];
    const uint32_t uQH = s2u(smb);
    const uint32_t uQL = uQH + 128*ALD*2;
    const uint32_t uKV = uQL + 128*ALD*2;

    int it = blockIdx.x, h = blockIdx.y, b = blockIdx.z;
    int tid = threadIdx.x, lane = tid & 31, w = tid >> 5;
    int g = lane >> 2, tq = lane & 3;
    int q0 = w * 16;

    const int lrow = lane & 7, lt = lane >> 3;
    const uint32_t a_off = (uint32_t)((q0 + ((lt & 1) << 3) + lrow) * (ALD*2) + (lt >> 1) * 16);
    const uint32_t b_off = (uint32_t)((((lt >> 1) << 3) + lrow) * (ALD*2) + (lt & 1) * 16);

    {
        int q = tid >> 1, seg = (tid & 1) * 32;
        const __nv_bfloat16* sH = g_qkH + ((size_t)b*NSP + it*128 + q)*512 + h*64 + seg;
        const __nv_bfloat16* sL = g_qkL + ((size_t)b*NSP + it*128 + q)*512 + h*64 + seg;
        uint32_t dH = uQH + (uint32_t)(q*ALD + seg)*2;
        uint32_t dL = uQL + (uint32_t)(q*ALD + seg)*2;
        CP16(dH, sH); CP16(dH+16, sH+8); CP16(dH+32, sH+16); CP16(dH+48, sH+24);
        CP16(dL, sL); CP16(dL+16, sL+8); CP16(dL+32, sL+16); CP16(dL+48, sL+24);
    }
    auto stageKV = [&](int kt, int bi) {
        uint32_t base = uKV + (uint32_t)bi*4*KVB;
        {
            int key = tid >> 2, sg = (tid & 3) * 16;
            const __nv_bfloat16* sH = g_qkH + ((size_t)b*NSP + kt*64 + key)*512 + 256 + h*64 + sg;
            const __nv_bfloat16* sL = g_qkL + ((size_t)b*NSP + kt*64 + key)*512 + 256 + h*64 + sg;
            uint32_t dH = base + (uint32_t)(key*ALD + sg)*2;
            uint32_t dL = base + KVB + (uint32_t)(key*ALD + sg)*2;
            CP16(dH, sH); CP16(dH+16, sH+8);
            CP16(dL, sL); CP16(dL+16, sL+8);
        }
        {
            int d = tid >> 2, sg = (tid & 3) * 16;
            const __nv_bfloat16* sH = g_vH + ((size_t)b*CCH + h*64 + d)*NSP + kt*64 + sg;
            const __nv_bfloat16* sL = g_vL + ((size_t)b*CCH + h*64 + d)*NSP + kt*64 + sg;
            uint32_t dH = base + 2*KVB + (uint32_t)(d*ALD + sg)*2;
            uint32_t dL = base + 3*KVB + (uint32_t)(d*ALD + sg)*2;
            CP16(dH, sH); CP16(dH+16, sH+8);
            CP16(dL, sL); CP16(dL+16, sL+8);
        }
        asm volatile("cp.async.commit_group;" ::: "memory");
    };

    stageKV(0, 0);

    float m0 = -1e30f, m1 = -1e30f, l0 = 0.f, l1 = 0.f;
    float oacc[8][4] = {};

    for (int kt = 0; kt < 16; kt++) {
        int bi = kt & 1;
        if (kt + 1 < 16) {
            stageKV(kt + 1, bi ^ 1);
            asm volatile("cp.async.wait_group 1;" ::: "memory");
        } else {
            asm volatile("cp.async.wait_group 0;" ::: "memory");
        }
        __syncthreads();

        uint32_t uKH = uKV + (uint32_t)bi*4*KVB;
        uint32_t uKL = uKH + KVB, uVH = uKH + 2*KVB, uVL = uKH + 3*KVB;

        float sacc[8][4] = {};
        #pragma unroll
        for (int kc = 0; kc < 4; kc++) {
            uint32_t aH[4], aL[4];
            ldsm4(aH[0], aH[1], aH[2], aH[3], uQH + a_off + kc*32);
            ldsm4(aL[0], aL[1], aL[2], aL[3], uQL + a_off + kc*32);
            #pragma unroll
            for (int p = 0; p < 4; p++) {
                uint32_t h0, h1, h2, h3, x0, x1, x2, x3;
                ldsm4(h0, h1, h2, h3, uKH + b_off + p*16*(ALD*2) + kc*32);
                ldsm4(x0, x1, x2, x3, uKL + b_off + p*16*(ALD*2) + kc*32);
                MMA_B16(sacc[2*p  ], aH, h0, h1);
                MMA_B16(sacc[2*p  ], aH, x0, x1);
                MMA_B16(sacc[2*p  ], aL, h0, h1);
                MMA_B16(sacc[2*p+1], aH, h2, h3);
                MMA_B16(sacc[2*p+1], aH, x2, x3);
                MMA_B16(sacc[2*p+1], aL, h2, h3);
            }
        }

        float rm0 = -1e30f, rm1 = -1e30f;
        #pragma unroll
        for (int nf = 0; nf < 8; nf++) {
            rm0 = fmaxf(rm0, fmaxf(sacc[nf][0], sacc[nf][1]));
            rm1 = fmaxf(rm1, fmaxf(sacc[nf][2], sacc[nf][3]));
        }
        rm0 = fmaxf(rm0, __shfl_xor_sync(0xffffffffu, rm0, 1));
        rm0 = fmaxf(rm0, __shfl_xor_sync(0xffffffffu, rm0, 2));
        rm1 = fmaxf(rm1, __shfl_xor_sync(0xffffffffu, rm1, 1));
        rm1 = fmaxf(rm1, __shfl_xor_sync(0xffffffffu, rm1, 2));
        float mn0 = fmaxf(m0, rm0), mn1 = fmaxf(m1, rm1);
        float al0 = __expf(m0 - mn0), al1 = __expf(m1 - mn1);
        m0 = mn0; m1 = mn1;
        float ls0 = 0.f, ls1 = 0.f;
        #pragma unroll
        for (int nf = 0; nf < 8; nf++) {
            sacc[nf][0] = __expf(sacc[nf][0] - mn0);
            sacc[nf][1] = __expf(sacc[nf][1] - mn0);
            sacc[nf][2] = __expf(sacc[nf][2] - mn1);
            sacc[nf][3] = __expf(sacc[nf][3] - mn1);
            ls0 += sacc[nf][0] + sacc[nf][1];
            ls1 += sacc[nf][2] + sacc[nf][3];
        }
        ls0 += __shfl_xor_sync(0xffffffffu, ls0, 1);
        ls0 += __shfl_xor_sync(0xffffffffu, ls0, 2);
        ls1 += __shfl_xor_sync(0xffffffffu, ls1, 1);
        ls1 += __shfl_xor_sync(0xffffffffu, ls1, 2);
        l0 = l0 * al0 + ls0;
        l1 = l1 * al1 + ls1;
        #pragma unroll
        for (int nf = 0; nf < 8; nf++) {
            oacc[nf][0] *= al0; oacc[nf][1] *= al0;
            oacc[nf][2] *= al1; oacc[nf][3] *= al1;
        }

        uint32_t pH[4][4], pL[4][4];
        #pragma unroll
        for (int c = 0; c < 4; c++) {
            pack2(sacc[2*c  ][0], sacc[2*c  ][1], pH[c][0], pL[c][0]);
            pack2(sacc[2*c  ][2], sacc[2*c  ][3], pH[c][1], pL[c][1]);
            pack2(sacc[2*c+1][0], sacc[2*c+1][1], pH[c][2], pL[c][2]);
            pack2(sacc[2*c+1][2], sacc[2*c+1][3], pH[c][3], pL[c][3]);
        }

        #pragma unroll
        for (int c = 0; c < 4; c++) {
            #pragma unroll
            for (int p = 0; p < 4; p++) {
                uint32_t h0, h1, h2, h3, x0, x1, x2, x3;
                ldsm4(h0, h1, h2, h3, uVH + b_off + p*16*(ALD*2) + c*32);
                ldsm4(x0, x1, x2, x3, uVL + b_off + p*16*(ALD*2) + c*32);
                MMA_B16(oacc[2*p  ], pH[c], h0, h1);
                MMA_B16(oacc[2*p  ], pH[c], x0, x1);
                MMA_B16(oacc[2*p  ], pL[c], h0, h1);
                MMA_B16(oacc[2*p+1], pH[c], h2, h3);
                MMA_B16(oacc[2*p+1], pH[c], x2, x3);
                MMA_B16(oacc[2*p+1], pL[c], h2, h3);
            }
        }
        __syncthreads();
    }

    float inv0 = 1.f / l0, inv1 = 1.f / l1;
    float* OS = (float*)smb;
    #pragma unroll
    for (int nf = 0; nf < 8; nf++) {
        int d = nf*8 + 2*tq;
        OS[(d  )*128 + q0 + g    ] = oacc[nf][0] * inv0;
        OS[(d+1)*128 + q0 + g    ] = oacc[nf][1] * inv0;
        OS[(d  )*128 + q0 + g + 8] = oacc[nf][2] * inv1;
        OS[(d+1)*128 + q0 + g + 8] = oacc[nf][3] * inv1;
    }
    __syncthreads();
    {
        int d = tid >> 2, q32 = (tid & 3) * 32;
        float* ob = outp + ((size_t)b*CCH + h*DKD + d)*NSP + it*128 + q32;
        #pragma unroll
        for (int j = 0; j < 8; j++)
            *(float4*)(ob + j*4) = *(const float4*)&OS[d*128 + q32 + j*4];
    }
}

// ---------- launch ----------
#define ATTN_SMEM ((2*128 + 8*64)*ALD*2)
#define GEMM_SMEM (4*128*ALD*2)
#define GEMM_CP_SMEM (8*128*ALD2*2)

extern "C" void kernel_launch(void* const* d_in, const int* in_sizes, int n_in,
                              void* d_out, int out_size) {
    const float* x     = (const float*)d_in[0];
    const float* qkv_w = (const float*)d_in[1];
    const float* uh_w  = (const float*)d_in[2];
    const float* uh_b  = (const float*)d_in[3];
    const float* n1_w  = (const float*)d_in[4];
    const float* n1_b  = (const float*)d_in[5];
    const float* n2_w  = (const float*)d_in[6];
    const float* n2_b  = (const float*)d_in[7];
    const float* f1_w  = (const float*)d_in[8];
    const float* f1_b  = (const float*)d_in[9];
    const float* f2_w  = (const float*)d_in[10];
    const float* f2_b  = (const float*)d_in[11];
    const float* g_at  = (const float*)d_in[12];
    const float* g_ff  = (const float*)d_in[13];
    float* out = (float*)d_out;

    float *attn_buf, *x2_buf;
    __nv_bfloat16 *wH, *wL, *aH, *aL, *h1H, *h1L;
    cudaGetSymbolAddress((void**)&attn_buf, g_attn);
    cudaGetSymbolAddress((void**)&x2_buf,   g_x2);
    cudaGetSymbolAddress((void**)&wH, g_wH);
    cudaGetSymbolAddress((void**)&wL, g_wL);
    cudaGetSymbolAddress((void**)&aH, g_aH);
    cudaGetSymbolAddress((void**)&aL, g_aL);
    cudaGetSymbolAddress((void**)&h1H, g_h1H);
    cudaGetSymbolAddress((void**)&h1L, g_h1L);

    cudaFuncSetAttribute(attn_mma, cudaFuncAttributeMaxDynamicSharedMemorySize, ATTN_SMEM);
    cudaFuncSetAttribute(gemm_cp<256,0>,  cudaFuncAttributeMaxDynamicSharedMemorySize, GEMM_CP_SMEM);
    cudaFuncSetAttribute(gemm_cp<256,4>,  cudaFuncAttributeMaxDynamicSharedMemorySize, GEMM_CP_SMEM);
    cudaFuncSetAttribute(gemm_cp<1024,3>, cudaFuncAttributeMaxDynamicSharedMemorySize, GEMM_CP_SMEM);
    cudaFuncSetAttribute(gemm_mma<256,1>, cudaFuncAttributeMaxDynamicSharedMemorySize, GEMM_SMEM);

    zero_stats_kernel<<<1, 32>>>();
    gn_stats_kernel<<<dim3(32, BSZ), 256>>>(x);
    convert_w_all<<<1536, 256>>>(qkv_w, uh_w, f1_w, f2_w);

    // GN1(x) -> token-major split
    prep_act<1><<<dim3(32, 8, BSZ), 256>>>(x, n1_w, n1_b);

    // qkv = qkv_w @ GN1(x) -> split Q/K token-major + V channel-major
    gemm_cp<256,0><<<dim3(8,6,BSZ), 256, GEMM_CP_SMEM>>>(
        wH + W_QKV, wL + W_QKV, aH, aL, nullptr, nullptr, nullptr, nullptr);

    attn_mma<<<dim3(8, NHH, BSZ), 256, ATTN_SMEM>>>(attn_buf);

    // x2 = x + g_at*(uh_w@attn + uh_b), + GN2 stats
    gemm_mma<256,1><<<dim3(8,2,BSZ), 256, GEMM_SMEM>>>(
        attn_buf, wH + W_UH, wL + W_UH, uh_b, x, g_at, x2_buf);

    // GN2(x2) -> token-major split (reuses g_aH/aL)
    prep_act<2><<<dim3(32, 8, BSZ), 256>>>(x2_buf, n2_w, n2_b);

    // h1 = silu(f1_w @ GN2(x2) + f1_b) -> token-major split h1
    gemm_cp<256,4><<<dim3(8,8,BSZ), 256, GEMM_CP_SMEM>>>(
        wH + W_F1, wL + W_F1, aH, aL, f1_b, nullptr, nullptr, nullptr);

    // out = x2 + g_ff*(f2_w@h1 + f2_b)
    gemm_cp<1024,3><<<dim3(8,2,BSZ), 256, GEMM_CP_SMEM>>>(
        wH + W_F2, wL + W_F2, h1H, h1L, f2_b, x2_buf, g_ff, out);
}